// round 12
// baseline (speedup 1.0000x reference)
#include <cuda_runtime.h>
#include <cstdint>

#define N_ 100000
#define E_ 3200000
#define NCAND 1024
#define CAP 2048
#define SCAN_B 256
#define NBLK ((N_ + SCAN_B - 1) / SCAN_B)   // 391

// ---------------- device scratch (static, zero-init; self-cleaning) -------------
__device__ float2 g_fst [N_*32];
__device__ float2 g_emb1[N_*32];
__device__ uint2  g_edge[E_];          // CSR records: (col, val bits), segmented
__device__ unsigned short g_rank[E_];  // within-segment rank | cls<<12
__device__ float  g_order0[N_];
__device__ float  g_order1[N_];
__device__ float  g_num1[N_];
__device__ unsigned g_cnt[N_];         // packed: deg | cnt_m1<<10 | cnt_m12<<20 (zeroed by scanC)
__device__ uint2  g_rowseg[N_];        // .x = rowptr, .y = cnt12 | cnt1<<10 | deg<<20
__device__ int    g_blocktot[NBLK];
__device__ int    g_blockoff[NBLK];
__device__ unsigned g_keys[N_];
__device__ unsigned g_hist64[65536];   // zeroed by thresh after use
__device__ unsigned g_prefix;
__device__ int g_ticket;               // reset by selsort last block
__device__ int g_ticket2;              // reset by scanA scanner block
__device__ int g_selcount;             // reset by selsort last block
__device__ unsigned long long g_cand[CAP];

// ---------------- Threefry-2x32 (20 rounds, 5 key injections) -------------------
#define TFR(a,b,r) { a += b; b = ((b << (r)) | (b >> (32-(r)))); b ^= a; }

__host__ __device__ __forceinline__ void tf2x32(unsigned k0, unsigned k1,
                                                unsigned& x0, unsigned& x1) {
    unsigned k2 = k0 ^ k1 ^ 0x1BD11BDAu;
    x0 += k0; x1 += k1;
    TFR(x0,x1,13) TFR(x0,x1,15) TFR(x0,x1,26) TFR(x0,x1,6)
    x0 += k1; x1 += k2 + 1u;
    TFR(x0,x1,17) TFR(x0,x1,29) TFR(x0,x1,16) TFR(x0,x1,24)
    x0 += k2; x1 += k0 + 2u;
    TFR(x0,x1,13) TFR(x0,x1,15) TFR(x0,x1,26) TFR(x0,x1,6)
    x0 += k0; x1 += k1 + 3u;
    TFR(x0,x1,17) TFR(x0,x1,29) TFR(x0,x1,16) TFR(x0,x1,24)
    x0 += k1; x1 += k2 + 4u;
    TFR(x0,x1,13) TFR(x0,x1,15) TFR(x0,x1,26) TFR(x0,x1,6)
    x0 += k2; x1 += k0 + 5u;
}

static void jax_split_part(unsigned k0, unsigned k1, unsigned* nk, unsigned* sk) {
    unsigned a0 = 0u, a1 = 0u; tf2x32(k0, k1, a0, a1);
    unsigned b0 = 0u, b1 = 1u; tf2x32(k0, k1, b0, b1);
    nk[0] = a0; nk[1] = a1;
    sk[0] = b0; sk[1] = b1;
}

__device__ __forceinline__ unsigned rb32(unsigned k0, unsigned k1, unsigned i) {
    unsigned x0 = 0u, x1 = i;
    tf2x32(k0, k1, x0, x1);
    return x0 ^ x1;
}

// ---------------- kernels -------------------------------------------------------

// RNG masks + packed per-row class counts, 2 edges per thread (4 independent
// threefry chains for ALU-pipe ILP). The atomic's return value yields the
// edge's within-segment rank. Requires g_cnt == 0 on entry (scanC restores it).
__global__ void k_count(const int* __restrict__ rows,
                        unsigned a0, unsigned a1, unsigned b0, unsigned b1) {
    int p = blockIdx.x * blockDim.x + threadIdx.x;
    if (p >= E_ / 2) return;
    unsigned e0 = 2u * (unsigned)p, e1 = e0 + 1u;
    unsigned uA = rb32(a0, a1, e0);
    unsigned uB = rb32(a0, a1, e1);
    unsigned uC = rb32(b0, b1, e0);
    unsigned uD = rb32(b0, b1, e1);
    int2 rr = __ldg((const int2*)rows + p);

    unsigned m1a  = (uA >= 0x80000000u) ? 1u : 0u;
    unsigned m12a = (m1a && uC >= 0xC0000000u) ? 1u : 0u;
    unsigned m1b  = (uB >= 0x80000000u) ? 1u : 0u;
    unsigned m12b = (m1b && uD >= 0xC0000000u) ? 1u : 0u;

    unsigned oldA = atomicAdd(&g_cnt[rr.x], 1u + (m1a << 10) + (m12a << 20));
    unsigned oldB = atomicAdd(&g_cnt[rr.y], 1u + (m1b << 10) + (m12b << 20));

    unsigned d0a = oldA & 1023u, dm1a = (oldA >> 10) & 1023u, dm12a = (oldA >> 20) & 1023u;
    unsigned clsA  = m12a ? 0u : (m1a ? 1u : 2u);
    unsigned rankA = m12a ? dm12a : (m1a ? (dm1a - dm12a) : (d0a - dm1a));

    unsigned d0b = oldB & 1023u, dm1b = (oldB >> 10) & 1023u, dm12b = (oldB >> 20) & 1023u;
    unsigned clsB  = m12b ? 0u : (m1b ? 1u : 2u);
    unsigned rankB = m12b ? dm12b : (m1b ? (dm1b - dm12b) : (d0b - dm1b));

    ((unsigned*)g_rank)[p] = (rankA | (clsA << 12)) | ((rankB | (clsB << 12)) << 16);
}

// ---- fused block reduce + inter-block scan (last-block ticket) ----
__global__ void k_scanA() {
    __shared__ int s[SCAN_B];
    __shared__ int s_last;
    int tid = threadIdx.x;
    int i = blockIdx.x * SCAN_B + tid;
    s[tid] = (i < N_) ? (int)(g_cnt[i] & 1023u) : 0;
    __syncthreads();
    for (int off = SCAN_B / 2; off > 0; off >>= 1) {
        if (tid < off) s[tid] += s[tid + off];
        __syncthreads();
    }
    if (tid == 0) g_blocktot[blockIdx.x] = s[0];
    __threadfence();
    __syncthreads();
    if (tid == 0)
        s_last = (atomicAdd(&g_ticket2, 1) == NBLK - 1) ? 1 : 0;
    __syncthreads();
    if (!s_last) return;

    if (tid == 0) g_ticket2 = 0;   // self-clean for next replay

    // last block: exclusive scan of 391 block totals (padded to 512, 2/thread)
    __shared__ int t2[512];
    int a0 = (tid < NBLK) ? *((volatile int*)&g_blocktot[tid]) : 0;
    int a1 = (tid + 256 < NBLK) ? *((volatile int*)&g_blocktot[tid + 256]) : 0;
    t2[tid] = a0; t2[tid + 256] = a1;
    __syncthreads();
    for (int off = 1; off < 512; off <<= 1) {
        int u0 = t2[tid]       + ((tid >= off)       ? t2[tid - off]       : 0);
        int u1 = t2[tid + 256] + ((tid + 256 >= off) ? t2[tid + 256 - off] : 0);
        __syncthreads();
        t2[tid] = u0; t2[tid + 256] = u1;
        __syncthreads();
    }
    if (tid < NBLK)       g_blockoff[tid]       = t2[tid] - a0;
    if (tid + 256 < NBLK) g_blockoff[tid + 256] = t2[tid + 256] - a1;
}

__global__ void k_scanC() {
    __shared__ int s[SCAN_B];
    int tid = threadIdx.x;
    int i = blockIdx.x * SCAN_B + tid;
    unsigned pc = (i < N_) ? g_cnt[i] : 0u;
    int d = (int)(pc & 1023u);
    s[tid] = d;
    __syncthreads();
    for (int off = 1; off < SCAN_B; off <<= 1) {
        int v = s[tid];
        if (tid >= off) v += s[tid - off];
        __syncthreads();
        s[tid] = v;
        __syncthreads();
    }
    if (i < N_) {
        unsigned rp = (unsigned)(g_blockoff[blockIdx.x] + s[tid] - d);
        unsigned cnt1  = (pc >> 10) & 1023u;
        unsigned cnt12 = (pc >> 20) & 1023u;
        g_rowseg[i] = make_uint2(rp, cnt12 | (cnt1 << 10) | ((unsigned)d << 20));
        g_cnt[i] = 0u;                 // self-clean for next replay
    }
}

// scatter edges into segmented CSR slots: [m12][m1-only][dropped] — atomic-free,
// 4 edges per thread with vectorized input loads.
__global__ void k_fill(const int* __restrict__ rows, const int* __restrict__ cols,
                       const float* __restrict__ vals) {
    int p = blockIdx.x * blockDim.x + threadIdx.x;
    if (p >= E_ / 4) return;
    int4   rr = __ldg((const int4*)rows + p);
    int4   cc = __ldg((const int4*)cols + p);
    float4 vv = __ldg((const float4*)vals + p);
    uint2  rk4 = __ldg((const uint2*)g_rank + p);

    unsigned rks[4] = { rk4.x & 0xFFFFu, rk4.x >> 16, rk4.y & 0xFFFFu, rk4.y >> 16 };
    int      rrs[4] = { rr.x, rr.y, rr.z, rr.w };
    unsigned ccs[4] = { (unsigned)cc.x, (unsigned)cc.y, (unsigned)cc.z, (unsigned)cc.w };
    float    vvs[4] = { vv.x, vv.y, vv.z, vv.w };

    #pragma unroll
    for (int j = 0; j < 4; j++) {
        unsigned rk = rks[j];
        unsigned cls = rk >> 12, within = rk & 0xFFFu;
        uint2 rs = __ldg(&g_rowseg[rrs[j]]);
        unsigned cnt12 = rs.y & 1023u, cnt1 = (rs.y >> 10) & 1023u;
        unsigned segbase = (cls == 0u) ? 0u : ((cls == 1u) ? cnt12 : cnt1);
        g_edge[rs.x + segbase + within] = make_uint2(ccs[j], __float_as_uint(vvs[j]));
    }
}

// ---- gather SpMM passes: 1 warp per row, float2 per lane ----
template<int PASS>
__global__ void k_pass(const float2* __restrict__ embeds, float* __restrict__ out,
                       unsigned n0, unsigned n1) {
    unsigned t = blockIdx.x * blockDim.x + threadIdx.x;
    int w = (int)(t >> 5);
    int c = (int)(t & 31u);
    if (w >= N_) return;

    const float2* xin = (PASS == 1) ? embeds : (PASS == 2 ? g_fst : g_emb1);
    const float* numin = (PASS == 2) ? g_order0 : g_num1;

    uint2 rs = __ldg(&g_rowseg[w]);
    int beg = (int)rs.x;
    int cnt = (PASS == 1) ? (int)((rs.y >> 20) & 1023u)
            : (PASS == 2) ? (int)((rs.y >> 10) & 1023u)
                          : (int)(rs.y & 1023u);

    float ax = 0.f, ay = 0.f;
    float ns = 0.f, o1acc = 0.f;

    #pragma unroll 4
    for (int e = beg; e < beg + cnt; ++e) {
        uint2 er = __ldg(&g_edge[e]);
        float v = __uint_as_float(er.y);
        float2 x = __ldg(&xin[(size_t)er.x * 32 + c]);
        ax += v * x.x; ay += v * x.y;
        if (PASS == 1) ns += v;
        else           ns += v * __ldg(&numin[er.x]);
        if (PASS == 2) o1acc += v;
    }

    size_t idx = (size_t)w * 32 + c;

    if (PASS == 1) {
        float2 b = __ldg(&embeds[idx]);
        g_fst[idx] = make_float2(ax - b.x, ay - b.y);
        if (c == 0) g_order0[w] = ns;
    } else if (PASS == 2) {
        float o = __ldg(&g_order0[w]);
        float f = 1.0f + o;
        float2 p = __ldg(&g_fst[idx]);
        g_emb1[idx] = make_float2(ax - f * p.x, ay - f * p.y);
        if (c == 0) { g_num1[w] = ns - 2.0f * o; g_order1[w] = o1acc; }
    } else {
        float o1  = __ldg(&g_order1[w]);
        float o0  = __ldg(&g_order0[w]);
        float n1v = __ldg(&g_num1[w]);
        float f = 1.0f + o1;
        float2 e1 = __ldg(&g_emb1[idx]);
        float2 p  = __ldg(&g_fst[idx]);
        float2 b  = __ldg(&embeds[idx]);
        float e2x = ax - f * e1.x, e2y = ay - f * e1.y;
        float num2 = ns - n1v - o1;
        float inv = 1.0f / (o0 + n1v + num2 + 1e-8f);
        float sx = (p.x + e1.x + e2x) * inv;
        float sy = (p.y + e1.y + e2y) * inv;
        float sa = sx * sx + sy * sy;
        float sb = b.x * b.x + b.y * b.y;
        float dp = sx * b.x + sy * b.y;
        for (int off = 16; off > 0; off >>= 1) {
            sa += __shfl_down_sync(0xFFFFFFFFu, sa, off);
            sb += __shfl_down_sync(0xFFFFFFFFu, sb, off);
            dp += __shfl_down_sync(0xFFFFFFFFu, dp, off);
        }
        if (c == 0) {
            float na = sqrtf(sa); if (na < 1e-12f) na = 1e-12f;
            float nb = sqrtf(sb); if (nb < 1e-12f) nb = 1e-12f;
            float score = dp / (na * nb);
            unsigned bits = rb32(n0, n1, (unsigned)w);
            float u = __uint_as_float(0x3F800000u | (bits >> 9)) - 1.0f;
            score += -logf(-logf(u));
            out[w] = score;
            unsigned kk = __float_as_uint(score);
            kk = (kk & 0x80000000u) ? ~kk : (kk | 0x80000000u);
            g_keys[w] = kk;
            atomicAdd(&g_hist64[kk >> 16], 1u);
        }
    }
}

// ---- single-block threshold finder; zeroes g_hist64 afterward (self-clean) ----
__global__ void k_thresh() {
    __shared__ unsigned sup[1024];
    int t = threadIdx.x;
    sup[t] = 0u;
    __syncthreads();
    for (int j = 0; j < 64; j++) {
        int b = j * 1024 + t;
        unsigned h = g_hist64[b];
        if (h) atomicAdd(&sup[b >> 6], h);
    }
    __syncthreads();
    for (int off = 1; off < 1024; off <<= 1) {
        unsigned v = sup[t] + ((t + off < 1024) ? sup[t + off] : 0u);
        __syncthreads();
        sup[t] = v;
        __syncthreads();
    }
    unsigned sufHere = sup[t];
    unsigned sufNext = (t < 1023) ? sup[t + 1] : 0u;
    if (sufHere >= NCAND && sufNext < NCAND) {
        unsigned acc = sufNext;
        int T = t * 64;
        for (int b = 63; b >= 0; --b) {
            acc += g_hist64[t * 64 + b];
            if (acc >= NCAND) { T = t * 64 + b; break; }
        }
        g_prefix = ((unsigned)T) << 16;
    }
    __syncthreads();
    // self-clean: zero the histogram for the next replay
    for (int j = 0; j < 64; j++)
        g_hist64[j * 1024 + t] = 0u;
}

// ---- fused select + sort: grid selects candidates; last block bitonic-sorts ----
__global__ void k_selsort(float* __restrict__ out) {
    __shared__ unsigned long long sm[CAP];
    __shared__ int s_last;
    int tid = threadIdx.x;
    unsigned pref = g_prefix;

    int i = blockIdx.x * blockDim.x + tid;
    if (i < N_) {
        unsigned k = g_keys[i];
        if (k >= pref) {
            int p = atomicAdd(&g_selcount, 1);
            if (p < CAP)
                g_cand[p] = (((unsigned long long)k) << 32) | (unsigned)(~(unsigned)i);
        }
    }
    __threadfence();
    __syncthreads();
    if (tid == 0)
        s_last = (atomicAdd(&g_ticket, 1) == (int)gridDim.x - 1) ? 1 : 0;
    __syncthreads();
    if (!s_last) return;

    int cnt = *((volatile int*)&g_selcount); if (cnt > CAP) cnt = CAP;
    if (tid == 0) { g_selcount = 0; g_ticket = 0; }   // self-clean
    for (int s = 0; s < CAP / 1024; s++) {
        int j = tid + s * 1024;
        sm[j] = (j < cnt) ? *((volatile unsigned long long*)&g_cand[j]) : 0ull;
    }
    __syncthreads();
    for (int k = 2; k <= CAP; k <<= 1) {
        for (int j = k >> 1; j > 0; j >>= 1) {
            for (int s = 0; s < CAP / 1024; s++) {
                int a = tid + s * 1024;
                int l = a ^ j;
                if (l > a) {
                    unsigned long long va = sm[a], vb = sm[l];
                    bool up = ((a & k) == 0);
                    if ((va < vb) == up) { sm[a] = vb; sm[l] = va; }
                }
            }
            __syncthreads();
        }
    }
    unsigned idx = ~((unsigned)sm[tid]);
    out[N_ + tid] = (float)idx;
}

// ---------------- launch --------------------------------------------------------
extern "C" void kernel_launch(void* const* d_in, const int* in_sizes, int n_in,
                              void* d_out, int out_size) {
    const int*   rows   = (const int*)d_in[0];
    const int*   cols   = (const int*)d_in[1];
    const float* vals   = (const float*)d_in[2];
    const float* embeds = (const float*)d_in[3];
    float* out = (float*)d_out;

    // key chain (partitionable): key(42) -> (split) kd1 -> (split) kd2 -> (split) kn
    unsigned k0 = 0u, k1 = 42u, nk[2], kd1[2], kd2[2], kn[2];
    jax_split_part(k0, k1, nk, kd1); k0 = nk[0]; k1 = nk[1];
    jax_split_part(k0, k1, nk, kd2); k0 = nk[0]; k1 = nk[1];
    jax_split_part(k0, k1, nk, kn);

    const int B = 256;
    const int gN32 = (N_ * 32 + B - 1) / B;
    const int gE2  = (E_ / 2 + B - 1) / B;
    const int gE4  = (E_ / 4 + B - 1) / B;
    const int gS   = (N_ + 1023) / 1024;

    k_count<<<gE2, B>>>(rows, kd1[0], kd1[1], kd2[0], kd2[1]);
    k_scanA<<<NBLK, SCAN_B>>>();
    k_scanC<<<NBLK, SCAN_B>>>();
    k_fill<<<gE4, B>>>(rows, cols, vals);     // atomic-free, 4 edges/thread

    k_pass<1><<<gN32, B>>>((const float2*)embeds, out, kn[0], kn[1]);
    k_pass<2><<<gN32, B>>>((const float2*)embeds, out, kn[0], kn[1]);
    k_pass<3><<<gN32, B>>>((const float2*)embeds, out, kn[0], kn[1]);

    k_thresh<<<1, 1024>>>();
    k_selsort<<<gS, 1024>>>(out);
}

// round 13
// speedup vs baseline: 1.0044x; 1.0044x over previous
#include <cuda_runtime.h>
#include <cstdint>

#define N_ 100000
#define E_ 3200000
#define NCAND 1024
#define CAP 2048
#define SCAN_B 256
#define NBLK ((N_ + SCAN_B - 1) / SCAN_B)   // 391

// ---------------- device scratch (static, zero-init; self-cleaning) -------------
__device__ float2 g_fst [N_*32];
__device__ float2 g_emb1[N_*32];
__device__ uint2  g_edge[E_];          // CSR records: (col, val bits), segmented
__device__ unsigned short g_rank[E_];  // within-segment rank | cls<<12
__device__ float  g_order0[N_];
__device__ float  g_order1[N_];
__device__ float  g_num1[N_];
__device__ unsigned g_cnt[N_];         // packed: deg | cnt_m1<<10 | cnt_m12<<20 (zeroed by k_scan)
__device__ uint2  g_rowseg[N_];        // .x = rowptr, .y = cnt12 | cnt1<<10 | deg<<20
__device__ int    g_blocktot[NBLK];
__device__ unsigned g_scanstate[NBLK]; // 0 = pending, (1<<31)|prefix (self-cleaned)
__device__ unsigned g_keys[N_];
__device__ unsigned g_hist64[65536];   // zeroed by thresh after use
__device__ unsigned g_prefix;
__device__ int g_ticket;               // reset by selsort last block
__device__ int g_ticket2;              // reset by scan scanner block
__device__ int g_selcount;             // reset by selsort last block
__device__ unsigned long long g_cand[CAP];

// ---------------- Threefry-2x32 (20 rounds, 5 key injections) -------------------
#define TFR(a,b,r) { a += b; b = ((b << (r)) | (b >> (32-(r)))); b ^= a; }

__host__ __device__ __forceinline__ void tf2x32(unsigned k0, unsigned k1,
                                                unsigned& x0, unsigned& x1) {
    unsigned k2 = k0 ^ k1 ^ 0x1BD11BDAu;
    x0 += k0; x1 += k1;
    TFR(x0,x1,13) TFR(x0,x1,15) TFR(x0,x1,26) TFR(x0,x1,6)
    x0 += k1; x1 += k2 + 1u;
    TFR(x0,x1,17) TFR(x0,x1,29) TFR(x0,x1,16) TFR(x0,x1,24)
    x0 += k2; x1 += k0 + 2u;
    TFR(x0,x1,13) TFR(x0,x1,15) TFR(x0,x1,26) TFR(x0,x1,6)
    x0 += k0; x1 += k1 + 3u;
    TFR(x0,x1,17) TFR(x0,x1,29) TFR(x0,x1,16) TFR(x0,x1,24)
    x0 += k1; x1 += k2 + 4u;
    TFR(x0,x1,13) TFR(x0,x1,15) TFR(x0,x1,26) TFR(x0,x1,6)
    x0 += k2; x1 += k0 + 5u;
}

static void jax_split_part(unsigned k0, unsigned k1, unsigned* nk, unsigned* sk) {
    unsigned a0 = 0u, a1 = 0u; tf2x32(k0, k1, a0, a1);
    unsigned b0 = 0u, b1 = 1u; tf2x32(k0, k1, b0, b1);
    nk[0] = a0; nk[1] = a1;
    sk[0] = b0; sk[1] = b1;
}

__device__ __forceinline__ unsigned rb32(unsigned k0, unsigned k1, unsigned i) {
    unsigned x0 = 0u, x1 = i;
    tf2x32(k0, k1, x0, x1);
    return x0 ^ x1;
}

// ---------------- kernels -------------------------------------------------------

// RNG masks + packed per-row class counts; the atomic's return value yields the
// edge's within-segment rank. Requires g_cnt == 0 on entry (k_scan restores it).
__global__ void k_count(const int* __restrict__ rows,
                        unsigned a0, unsigned a1, unsigned b0, unsigned b1) {
    int e = blockIdx.x * blockDim.x + threadIdx.x;
    if (e >= E_) return;
    unsigned u1 = rb32(a0, a1, (unsigned)e);
    unsigned u2 = rb32(b0, b1, (unsigned)e);
    unsigned m1  = (u1 >= 0x80000000u) ? 1u : 0u;           // keep prob 0.5
    unsigned m12 = (m1 && u2 >= 0xC0000000u) ? 1u : 0u;     // joint keep
    int r = __ldg(rows + e);
    unsigned old = atomicAdd(&g_cnt[r], 1u + (m1 << 10) + (m12 << 20));
    unsigned d0   = old & 1023u;
    unsigned dm1  = (old >> 10) & 1023u;
    unsigned dm12 = (old >> 20) & 1023u;
    unsigned cls  = m12 ? 0u : (m1 ? 1u : 2u);
    unsigned rank = m12 ? dm12 : (m1 ? (dm1 - dm12) : (d0 - dm1));
    g_rank[e] = (unsigned short)(rank | (cls << 12));
}

// ---- single-kernel scan: per-block scan + scanner-block prefix publish ----
// All NBLK=391 blocks are resident simultaneously (100K threads << chip). The
// last block to ticket scans all aggregates and publishes every block's
// exclusive prefix with a flag bit; other blocks spin only on their own word.
// Writes g_rowseg and self-cleans g_cnt and g_scanstate.
__global__ void k_scan() {
    __shared__ int s[SCAN_B];
    __shared__ unsigned s_base;
    __shared__ int s_scanner;
    int tid = threadIdx.x;
    int bid = blockIdx.x;
    int i = bid * SCAN_B + tid;
    unsigned pc = (i < N_) ? g_cnt[i] : 0u;
    int d = (int)(pc & 1023u);
    s[tid] = d;
    __syncthreads();
    for (int off = 1; off < SCAN_B; off <<= 1) {
        int v = s[tid];
        if (tid >= off) v += s[tid - off];
        __syncthreads();
        s[tid] = v;
        __syncthreads();
    }
    int total = s[SCAN_B - 1];

    if (tid == 0) {
        g_blocktot[bid] = total;
        __threadfence();
        s_scanner = (atomicAdd(&g_ticket2, 1) == NBLK - 1) ? 1 : 0;
    }
    __syncthreads();

    if (s_scanner) {
        if (tid == 0) g_ticket2 = 0;   // self-clean
        __shared__ int t2[512];
        int a0 = (tid < NBLK) ? *((volatile int*)&g_blocktot[tid]) : 0;
        int a1 = (tid + 256 < NBLK) ? *((volatile int*)&g_blocktot[tid + 256]) : 0;
        t2[tid] = a0; t2[tid + 256] = a1;
        __syncthreads();
        for (int off = 1; off < 512; off <<= 1) {
            int u0 = t2[tid]       + ((tid >= off)       ? t2[tid - off]       : 0);
            int u1 = t2[tid + 256] + ((tid + 256 >= off) ? t2[tid + 256 - off] : 0);
            __syncthreads();
            t2[tid] = u0; t2[tid + 256] = u1;
            __syncthreads();
        }
        if (tid < NBLK)
            g_scanstate[tid] = (1u << 31) | (unsigned)(t2[tid] - a0);
        if (tid + 256 < NBLK)
            g_scanstate[tid + 256] = (1u << 31) | (unsigned)(t2[tid + 256] - a1);
        __threadfence();
        __syncthreads();
        if (tid == 0) {
            s_base = g_scanstate[bid] & 0x7FFFFFFFu;
            g_scanstate[bid] = 0u;     // self-clean own word
        }
    } else if (tid == 0) {
        unsigned st;
        do { st = *((volatile unsigned*)&g_scanstate[bid]); } while (!(st >> 31));
        s_base = st & 0x7FFFFFFFu;
        g_scanstate[bid] = 0u;         // self-clean own word
    }
    __syncthreads();

    if (i < N_) {
        unsigned rp = s_base + (unsigned)(s[tid] - d);
        unsigned cnt1  = (pc >> 10) & 1023u;
        unsigned cnt12 = (pc >> 20) & 1023u;
        g_rowseg[i] = make_uint2(rp, cnt12 | (cnt1 << 10) | ((unsigned)d << 20));
        g_cnt[i] = 0u;                 // self-clean for next replay
    }
}

// scatter edges into segmented CSR slots: [m12][m1-only][dropped] — atomic-free,
// 2 edges per thread with vectorized input loads.
__global__ void k_fill(const int* __restrict__ rows, const int* __restrict__ cols,
                       const float* __restrict__ vals) {
    int p = blockIdx.x * blockDim.x + threadIdx.x;
    if (p >= E_ / 2) return;
    int2   rr = __ldg((const int2*)rows + p);
    int2   cc = __ldg((const int2*)cols + p);
    float2 vv = __ldg((const float2*)vals + p);
    unsigned rk2 = __ldg((const unsigned*)g_rank + p);

    {
        unsigned rk = rk2 & 0xFFFFu;
        unsigned cls = rk >> 12, within = rk & 0xFFFu;
        uint2 rs = __ldg(&g_rowseg[rr.x]);
        unsigned cnt12 = rs.y & 1023u, cnt1 = (rs.y >> 10) & 1023u;
        unsigned segbase = (cls == 0u) ? 0u : ((cls == 1u) ? cnt12 : cnt1);
        g_edge[rs.x + segbase + within] =
            make_uint2((unsigned)cc.x, __float_as_uint(vv.x));
    }
    {
        unsigned rk = rk2 >> 16;
        unsigned cls = rk >> 12, within = rk & 0xFFFu;
        uint2 rs = __ldg(&g_rowseg[rr.y]);
        unsigned cnt12 = rs.y & 1023u, cnt1 = (rs.y >> 10) & 1023u;
        unsigned segbase = (cls == 0u) ? 0u : ((cls == 1u) ? cnt12 : cnt1);
        g_edge[rs.x + segbase + within] =
            make_uint2((unsigned)cc.y, __float_as_uint(vv.y));
    }
}

// ---- gather SpMM passes: 1 warp per row, float2 per lane ----
template<int PASS>
__global__ void k_pass(const float2* __restrict__ embeds, float* __restrict__ out,
                       unsigned n0, unsigned n1) {
    unsigned t = blockIdx.x * blockDim.x + threadIdx.x;
    int w = (int)(t >> 5);
    int c = (int)(t & 31u);
    if (w >= N_) return;

    const float2* xin = (PASS == 1) ? embeds : (PASS == 2 ? g_fst : g_emb1);
    const float* numin = (PASS == 2) ? g_order0 : g_num1;

    uint2 rs = __ldg(&g_rowseg[w]);
    int beg = (int)rs.x;
    int cnt = (PASS == 1) ? (int)((rs.y >> 20) & 1023u)
            : (PASS == 2) ? (int)((rs.y >> 10) & 1023u)
                          : (int)(rs.y & 1023u);

    float ax = 0.f, ay = 0.f;
    float ns = 0.f, o1acc = 0.f;

    #pragma unroll 4
    for (int e = beg; e < beg + cnt; ++e) {
        uint2 er = __ldg(&g_edge[e]);
        float v = __uint_as_float(er.y);
        float2 x = __ldg(&xin[(size_t)er.x * 32 + c]);
        ax += v * x.x; ay += v * x.y;
        if (PASS == 1) ns += v;
        else           ns += v * __ldg(&numin[er.x]);
        if (PASS == 2) o1acc += v;
    }

    size_t idx = (size_t)w * 32 + c;

    if (PASS == 1) {
        float2 b = __ldg(&embeds[idx]);
        g_fst[idx] = make_float2(ax - b.x, ay - b.y);
        if (c == 0) g_order0[w] = ns;
    } else if (PASS == 2) {
        float o = __ldg(&g_order0[w]);
        float f = 1.0f + o;
        float2 p = __ldg(&g_fst[idx]);
        g_emb1[idx] = make_float2(ax - f * p.x, ay - f * p.y);
        if (c == 0) { g_num1[w] = ns - 2.0f * o; g_order1[w] = o1acc; }
    } else {
        float o1  = __ldg(&g_order1[w]);
        float o0  = __ldg(&g_order0[w]);
        float n1v = __ldg(&g_num1[w]);
        float f = 1.0f + o1;
        float2 e1 = __ldg(&g_emb1[idx]);
        float2 p  = __ldg(&g_fst[idx]);
        float2 b  = __ldg(&embeds[idx]);
        float e2x = ax - f * e1.x, e2y = ay - f * e1.y;
        float num2 = ns - n1v - o1;
        float inv = 1.0f / (o0 + n1v + num2 + 1e-8f);
        float sx = (p.x + e1.x + e2x) * inv;
        float sy = (p.y + e1.y + e2y) * inv;
        float sa = sx * sx + sy * sy;
        float sb = b.x * b.x + b.y * b.y;
        float dp = sx * b.x + sy * b.y;
        for (int off = 16; off > 0; off >>= 1) {
            sa += __shfl_down_sync(0xFFFFFFFFu, sa, off);
            sb += __shfl_down_sync(0xFFFFFFFFu, sb, off);
            dp += __shfl_down_sync(0xFFFFFFFFu, dp, off);
        }
        if (c == 0) {
            float na = sqrtf(sa); if (na < 1e-12f) na = 1e-12f;
            float nb = sqrtf(sb); if (nb < 1e-12f) nb = 1e-12f;
            float score = dp / (na * nb);
            unsigned bits = rb32(n0, n1, (unsigned)w);
            float u = __uint_as_float(0x3F800000u | (bits >> 9)) - 1.0f;
            score += -logf(-logf(u));
            out[w] = score;
            unsigned kk = __float_as_uint(score);
            kk = (kk & 0x80000000u) ? ~kk : (kk | 0x80000000u);
            g_keys[w] = kk;
            atomicAdd(&g_hist64[kk >> 16], 1u);
        }
    }
}

// ---- single-block threshold finder; zeroes g_hist64 afterward (self-clean) ----
__global__ void k_thresh() {
    __shared__ unsigned sup[1024];
    int t = threadIdx.x;
    sup[t] = 0u;
    __syncthreads();
    for (int j = 0; j < 64; j++) {
        int b = j * 1024 + t;
        unsigned h = g_hist64[b];
        if (h) atomicAdd(&sup[b >> 6], h);
    }
    __syncthreads();
    for (int off = 1; off < 1024; off <<= 1) {
        unsigned v = sup[t] + ((t + off < 1024) ? sup[t + off] : 0u);
        __syncthreads();
        sup[t] = v;
        __syncthreads();
    }
    unsigned sufHere = sup[t];
    unsigned sufNext = (t < 1023) ? sup[t + 1] : 0u;
    if (sufHere >= NCAND && sufNext < NCAND) {
        unsigned acc = sufNext;
        int T = t * 64;
        for (int b = 63; b >= 0; --b) {
            acc += g_hist64[t * 64 + b];
            if (acc >= NCAND) { T = t * 64 + b; break; }
        }
        g_prefix = ((unsigned)T) << 16;
    }
    __syncthreads();
    // self-clean: zero the histogram for the next replay
    for (int j = 0; j < 64; j++)
        g_hist64[j * 1024 + t] = 0u;
}

// ---- fused select + sort: grid selects candidates; last block bitonic-sorts ----
__global__ void k_selsort(float* __restrict__ out) {
    __shared__ unsigned long long sm[CAP];
    __shared__ int s_last;
    int tid = threadIdx.x;
    unsigned pref = g_prefix;

    int i = blockIdx.x * blockDim.x + tid;
    if (i < N_) {
        unsigned k = g_keys[i];
        if (k >= pref) {
            int p = atomicAdd(&g_selcount, 1);
            if (p < CAP)
                g_cand[p] = (((unsigned long long)k) << 32) | (unsigned)(~(unsigned)i);
        }
    }
    __threadfence();
    __syncthreads();
    if (tid == 0)
        s_last = (atomicAdd(&g_ticket, 1) == (int)gridDim.x - 1) ? 1 : 0;
    __syncthreads();
    if (!s_last) return;

    int cnt = *((volatile int*)&g_selcount); if (cnt > CAP) cnt = CAP;
    if (tid == 0) { g_selcount = 0; g_ticket = 0; }   // self-clean
    for (int s = 0; s < CAP / 1024; s++) {
        int j = tid + s * 1024;
        sm[j] = (j < cnt) ? *((volatile unsigned long long*)&g_cand[j]) : 0ull;
    }
    __syncthreads();
    for (int k = 2; k <= CAP; k <<= 1) {
        for (int j = k >> 1; j > 0; j >>= 1) {
            for (int s = 0; s < CAP / 1024; s++) {
                int a = tid + s * 1024;
                int l = a ^ j;
                if (l > a) {
                    unsigned long long va = sm[a], vb = sm[l];
                    bool up = ((a & k) == 0);
                    if ((va < vb) == up) { sm[a] = vb; sm[l] = va; }
                }
            }
            __syncthreads();
        }
    }
    unsigned idx = ~((unsigned)sm[tid]);
    out[N_ + tid] = (float)idx;
}

// ---------------- launch --------------------------------------------------------
extern "C" void kernel_launch(void* const* d_in, const int* in_sizes, int n_in,
                              void* d_out, int out_size) {
    const int*   rows   = (const int*)d_in[0];
    const int*   cols   = (const int*)d_in[1];
    const float* vals   = (const float*)d_in[2];
    const float* embeds = (const float*)d_in[3];
    float* out = (float*)d_out;

    // key chain (partitionable): key(42) -> (split) kd1 -> (split) kd2 -> (split) kn
    unsigned k0 = 0u, k1 = 42u, nk[2], kd1[2], kd2[2], kn[2];
    jax_split_part(k0, k1, nk, kd1); k0 = nk[0]; k1 = nk[1];
    jax_split_part(k0, k1, nk, kd2); k0 = nk[0]; k1 = nk[1];
    jax_split_part(k0, k1, nk, kn);

    const int B = 256;
    const int gN32 = (N_ * 32 + B - 1) / B;
    const int gE   = (E_ + B - 1) / B;
    const int gE2  = (E_ / 2 + B - 1) / B;
    const int gS   = (N_ + 1023) / 1024;

    k_count<<<gE, B>>>(rows, kd1[0], kd1[1], kd2[0], kd2[1]);
    k_scan<<<NBLK, SCAN_B>>>();
    k_fill<<<gE2, B>>>(rows, cols, vals);

    k_pass<1><<<gN32, B>>>((const float2*)embeds, out, kn[0], kn[1]);  // <- profiled (index 3)
    k_pass<2><<<gN32, B>>>((const float2*)embeds, out, kn[0], kn[1]);
    k_pass<3><<<gN32, B>>>((const float2*)embeds, out, kn[0], kn[1]);

    k_thresh<<<1, 1024>>>();
    k_selsort<<<gS, 1024>>>(out);
}